// round 3
// baseline (speedup 1.0000x reference)
#include <cuda_runtime.h>
#include <cuda_fp16.h>
#include <cstdint>

// ---------------- fixed problem sizes ----------------
#define B_   4
#define T_   2048
#define S_   4096
#define KD   512
#define MQ_  (B_*T_)    // 8192
#define MK_  (B_*S_)    // 16384

// ---------------- GEMM tiling ----------------
#define BM 128
#define BN 256
#define BK 64
#define NCH (KD/BK)                      // 8 k-chunks
#define A_STAGE (BM*128)                 // 16 KB
#define B_STAGE (BN*128)                 // 32 KB
#define STAGE_BYTES (A_STAGE + B_STAGE)  // 48 KB
#define SMEM_BYTES  (2*STAGE_BYTES)      // 96 KB double buffered
#define NTHREADS 512

// ---------------- scratch (device globals; no allocation allowed) ----------------
__device__ __half g_xq[MQ_ * KD];
__device__ __half g_xk[MK_ * KD];
__device__ __half g_wq[KD * KD];
__device__ __half g_wk[KD * KD];
__device__ __half g_q [MQ_ * KD];
__device__ __half g_k [MK_ * KD];

// ---------------- helpers ----------------
#define SWZ(o) ((o) ^ (((o) >> 3) & 0x70))   // SW128 swizzle on 128B rows

__device__ __forceinline__ uint32_t smem_u32(const void* p) {
    uint32_t a;
    asm("{ .reg .u64 t; cvta.to.shared.u64 t, %1; cvt.u32.u64 %0, t; }"
        : "=r"(a) : "l"(p));
    return a;
}

__device__ __forceinline__ void cp16(uint32_t s, const void* g) {
    asm volatile("cp.async.cg.shared.global [%0], [%1], 16;" :: "r"(s), "l"(g));
}
#define CP_COMMIT() asm volatile("cp.async.commit_group;" ::: "memory")
#define CP_WAIT0()  asm volatile("cp.async.wait_group 0;" ::: "memory")
#define CP_WAIT1()  asm volatile("cp.async.wait_group 1;" ::: "memory")

__device__ __forceinline__ void ldsm4(uint32_t* r, uint32_t addr) {
    asm volatile("ldmatrix.sync.aligned.m8n8.x4.shared.b16 {%0,%1,%2,%3}, [%4];"
                 : "=r"(r[0]), "=r"(r[1]), "=r"(r[2]), "=r"(r[3]) : "r"(addr));
}

__device__ __forceinline__ void mma16816(float* c, const uint32_t* a,
                                         uint32_t b0, uint32_t b1) {
    asm volatile(
        "mma.sync.aligned.m16n8k16.row.col.f32.f16.f16.f32 "
        "{%0,%1,%2,%3}, {%4,%5,%6,%7}, {%8,%9}, {%0,%1,%2,%3};"
        : "+f"(c[0]), "+f"(c[1]), "+f"(c[2]), "+f"(c[3])
        : "r"(a[0]), "r"(a[1]), "r"(a[2]), "r"(a[3]), "r"(b0), "r"(b1));
}

// ---------------- fused fp32 -> fp16 convert for all 4 tensors ----------------
#define NQ4  (MQ_ * KD / 4)   // 1048576
#define NK4  (MK_ * KD / 4)   // 2097152
#define NW4  (KD * KD / 4)    // 65536
#define NTOT4 (NQ4 + NK4 + 2 * NW4)

__global__ void f2h_all(const float4* __restrict__ q, const float4* __restrict__ k,
                        const float4* __restrict__ wq, const float4* __restrict__ wk,
                        __half2* __restrict__ oq, __half2* __restrict__ ok,
                        __half2* __restrict__ owq, __half2* __restrict__ owk) {
    int i = blockIdx.x * blockDim.x + threadIdx.x;
    if (i >= NTOT4) return;
    const float4* src;
    __half2* dst;
    int j = i;
    if (j < NQ4) { src = q; dst = oq; }
    else if ((j -= NQ4) < NK4) { src = k; dst = ok; }
    else if ((j -= NK4) < NW4) { src = wq; dst = owq; }
    else { j -= NW4; src = wk; dst = owk; }
    float4 v = src[j];
    dst[j * 2 + 0] = __floats2half2_rn(v.x, v.y);
    dst[j * 2 + 1] = __floats2half2_rn(v.z, v.w);
}

// ---------------- fp16 GEMM:  D[m,n] = sum_k A[m,k] * B[n,k]  ----------------
// MODE 0 (PROJ, fused Q+K): blockIdx.x < qTiles -> set0 (Q), else set1 (K).
//   out = D + bias[n], fp16 store.
// MODE 1 (LOGITS): out = D * (1/64), mask[b,n] -> -inf, fp32 store.
template <int MODE>
__global__ __launch_bounds__(NTHREADS, 1) void hgemm(
    const __half* __restrict__ A0, const __half* __restrict__ B0,
    const float* __restrict__ bias0, __half* __restrict__ out0,
    const __half* __restrict__ A1, const __half* __restrict__ B1,
    const float* __restrict__ bias1, __half* __restrict__ out1,
    const unsigned char* __restrict__ mask, float* __restrict__ outF,
    int qTiles) {
    extern __shared__ char smem[];
    const uint32_t sb = smem_u32(smem);
    const int tid = threadIdx.x;
    const int wid = tid >> 5;
    const int l = tid & 31;
    const int wm = wid >> 2;      // 0..3 : 32-row slab
    const int wn = wid & 3;       // 0..3 : 64-col slab
    const int nt = blockIdx.y, bz = blockIdx.z;

    const __half* A;
    const __half* Bm;
    const float* bias;
    __half* outH;
    int mt;
    size_t aBase, bBase, outRow0;
    if (MODE == 0) {
        if ((int)blockIdx.x < qTiles) {
            A = A0; Bm = B0; bias = bias0; outH = out0; mt = blockIdx.x;
        } else {
            A = A1; Bm = B1; bias = bias1; outH = out1; mt = blockIdx.x - qTiles;
        }
        aBase = (size_t)mt * BM * KD;
        bBase = (size_t)nt * BN * KD;
        outRow0 = (size_t)mt * BM;
    } else {
        A = A0; Bm = B0; bias = nullptr; outH = nullptr; mt = blockIdx.x;
        aBase = ((size_t)bz * T_ + (size_t)mt * BM) * KD;
        bBase = ((size_t)bz * S_ + (size_t)nt * BN) * KD;
        outRow0 = (size_t)bz * T_ + (size_t)mt * BM;
    }

    float acc[2][8][4];
#pragma unroll
    for (int i = 0; i < 2; ++i)
#pragma unroll
        for (int j = 0; j < 8; ++j)
#pragma unroll
            for (int c = 0; c < 4; ++c) acc[i][j][c] = 0.f;

    // per-lane ldmatrix address components
    const int aRow = wm * 32 + (l & 15);
    const int aKsel = ((l >> 4) & 1) * 16;                  // bytes
    const int bRow = wn * 64 + (l & 7) + ((l >> 4) & 1) * 8;
    const int bKsel = ((l >> 3) & 1) * 16;                  // bytes

    auto load_tile = [&](int stg, int k0) {
        const uint32_t sA = sb + stg * STAGE_BYTES;
        const uint32_t sB = sA + A_STAGE;
#pragma unroll
        for (int t = 0; t < 2; ++t) {          // A: 1024 cp16
            int i = tid + t * NTHREADS;
            int r = i >> 3, c = i & 7;
            cp16(sA + SWZ((uint32_t)(r * 128 + c * 16)),
                 A + aBase + (size_t)r * KD + k0 + c * 8);
        }
#pragma unroll
        for (int t = 0; t < 4; ++t) {          // B: 2048 cp16
            int i = tid + t * NTHREADS;
            int r = i >> 3, c = i & 7;
            cp16(sB + SWZ((uint32_t)(r * 128 + c * 16)),
                 Bm + bBase + (size_t)r * KD + k0 + c * 8);
        }
    };

    load_tile(0, 0);
    CP_COMMIT();

    int stg = 0;
    for (int ch = 0; ch < NCH; ++ch) {
        if (ch + 1 < NCH) {
            load_tile(stg ^ 1, (ch + 1) * BK);
            CP_COMMIT();
            CP_WAIT1();
        } else {
            CP_WAIT0();
        }
        __syncthreads();

        const uint32_t sA = sb + stg * STAGE_BYTES;
        const uint32_t sB = sA + A_STAGE;
#pragma unroll
        for (int ks = 0; ks < BK / 16; ++ks) {
            uint32_t afr[2][4];
            uint32_t bfr[4][4];
#pragma unroll
            for (int mi = 0; mi < 2; ++mi)
                ldsm4(afr[mi], sA + SWZ((uint32_t)((aRow + mi * 16) * 128 +
                                                   ks * 32 + aKsel)));
#pragma unroll
            for (int nb = 0; nb < 4; ++nb)
                ldsm4(bfr[nb], sB + SWZ((uint32_t)((bRow + nb * 16) * 128 +
                                                   ks * 32 + bKsel)));
#pragma unroll
            for (int mi = 0; mi < 2; ++mi)
#pragma unroll
                for (int ni = 0; ni < 8; ++ni)
                    mma16816(acc[mi][ni], afr[mi], bfr[ni >> 1][(ni & 1) * 2],
                             bfr[ni >> 1][(ni & 1) * 2 + 1]);
        }
        __syncthreads();
        stg ^= 1;
    }

    // ---------------- epilogue ----------------
    const int gid = l >> 2, tig = l & 3;
#pragma unroll
    for (int mi = 0; mi < 2; ++mi) {
#pragma unroll
        for (int ni = 0; ni < 8; ++ni) {
            const int col = nt * BN + wn * 64 + ni * 8 + tig * 2;
#pragma unroll
            for (int h = 0; h < 2; ++h) {
                const int rloc = wm * 32 + mi * 16 + gid + h * 8;
                const size_t rowg = outRow0 + rloc;
                const float v0 = acc[mi][ni][h * 2 + 0];
                const float v1 = acc[mi][ni][h * 2 + 1];
                if (MODE == 0) {
                    float o0 = v0 + bias[col];
                    float o1 = v1 + bias[col + 1];
                    *(__half2*)(outH + rowg * KD + col) =
                        __floats2half2_rn(o0, o1);
                } else {
                    const unsigned char* mrow = mask + (size_t)bz * S_;
                    const float NEG_INF = __int_as_float(0xff800000);
                    float2 o;
                    o.x = mrow[col + 0] ? NEG_INF : v0 * 0.015625f;
                    o.y = mrow[col + 1] ? NEG_INF : v1 * 0.015625f;
                    *(float2*)(outF + rowg * (size_t)S_ + col) = o;
                }
            }
        }
    }
}

// ---------------- host launch ----------------
extern "C" void kernel_launch(void* const* d_in, const int* in_sizes, int n_in,
                              void* d_out, int out_size) {
    const float* query = (const float*)d_in[0];
    const float* keys = (const float*)d_in[1];
    const unsigned char* mask = (const unsigned char*)d_in[2];
    const float* q_w = (const float*)d_in[3];
    const float* q_b = (const float*)d_in[4];
    const float* k_w = (const float*)d_in[5];
    const float* k_b = (const float*)d_in[6];

    void *xq, *xk, *wq, *wk, *q, *k;
    cudaGetSymbolAddress(&xq, g_xq);
    cudaGetSymbolAddress(&xk, g_xk);
    cudaGetSymbolAddress(&wq, g_wq);
    cudaGetSymbolAddress(&wk, g_wk);
    cudaGetSymbolAddress(&q, g_q);
    cudaGetSymbolAddress(&k, g_k);

    cudaFuncSetAttribute(hgemm<0>, cudaFuncAttributeMaxDynamicSharedMemorySize,
                         SMEM_BYTES);
    cudaFuncSetAttribute(hgemm<1>, cudaFuncAttributeMaxDynamicSharedMemorySize,
                         SMEM_BYTES);

    // 1) fp32 -> fp16 converts (single fused launch)
    f2h_all<<<(NTOT4 + 255) / 256, 256>>>(
        (const float4*)query, (const float4*)keys, (const float4*)q_w,
        (const float4*)k_w, (__half2*)xq, (__half2*)xk, (__half2*)wq,
        (__half2*)wk);

    // 2) fused projections: Q tiles [0,64), K tiles [64,192)
    hgemm<0><<<dim3(MQ_ / BM + MK_ / BM, KD / BN, 1), NTHREADS, SMEM_BYTES>>>(
        (const __half*)xq, (const __half*)wq, q_b, (__half*)q,
        (const __half*)xk, (const __half*)wk, k_b, (__half*)k,
        nullptr, nullptr, MQ_ / BM);

    // 3) logits = (Q K^T) / 64, masked    [4, 2048, 4096] fp32
    hgemm<1><<<dim3(T_ / BM, S_ / BN, B_), NTHREADS, SMEM_BYTES>>>(
        (const __half*)q, (const __half*)k, nullptr, nullptr,
        nullptr, nullptr, nullptr, nullptr,
        mask, (float*)d_out, 0);
}

// round 4
// speedup vs baseline: 1.0064x; 1.0064x over previous
#include <cuda_runtime.h>
#include <cuda_fp16.h>
#include <cstdint>

// ---------------- fixed problem sizes ----------------
#define B_   4
#define T_   2048
#define S_   4096
#define KD   512
#define MQ_  (B_*T_)    // 8192
#define MK_  (B_*S_)    // 16384

// ---------------- GEMM tiling (R2-proven config) ----------------
#define BM 128
#define BN 128
#define BK 64
#define NCH (KD/BK)
#define STAGE_BYTES (BM*128 + BN*128)   // 32 KB
#define SMEM_BYTES  (2*STAGE_BYTES)     // 64 KB

// ---------------- scratch (device globals; no allocation allowed) ----------------
__device__ __half g_xq16[MQ_ * KD];
__device__ __half g_xk16[MK_ * KD];
__device__ __half g_wqT[KD * KD];
__device__ __half g_wkT[KD * KD];
__device__ __half g_M  [KD * KD];     // M'[e,d] = sum_j Wk[j,e] Wq[j,d]
__device__ __half g_Y  [MQ_ * KD];    // Y[t,e] = xq[t,:] @ M[:,e] / 64
__device__ float  g_u  [MQ_];
__device__ float  g_v  [MK_];
__device__ float  g_wu [KD];
__device__ float  g_wv [KD];
__device__ float  g_c;

// ---------------- helpers ----------------
#define SWZ(o) ((o) ^ (((o) >> 3) & 0x70))

__device__ __forceinline__ uint32_t smem_u32(const void* p) {
    uint32_t a;
    asm("{ .reg .u64 t; cvta.to.shared.u64 t, %1; cvt.u32.u64 %0, t; }"
        : "=r"(a) : "l"(p));
    return a;
}

__device__ __forceinline__ void cp16(uint32_t s, const void* g) {
    asm volatile("cp.async.cg.shared.global [%0], [%1], 16;" :: "r"(s), "l"(g));
}
#define CP_COMMIT() asm volatile("cp.async.commit_group;" ::: "memory")
#define CP_WAIT0()  asm volatile("cp.async.wait_group 0;" ::: "memory")
#define CP_WAIT1()  asm volatile("cp.async.wait_group 1;" ::: "memory")

__device__ __forceinline__ void ldsm4(uint32_t* r, uint32_t addr) {
    asm volatile("ldmatrix.sync.aligned.m8n8.x4.shared.b16 {%0,%1,%2,%3}, [%4];"
                 : "=r"(r[0]), "=r"(r[1]), "=r"(r[2]), "=r"(r[3]) : "r"(addr));
}

__device__ __forceinline__ void mma16816(float* c, const uint32_t* a,
                                         uint32_t b0, uint32_t b1) {
    asm volatile(
        "mma.sync.aligned.m16n8k16.row.col.f32.f16.f16.f32 "
        "{%0,%1,%2,%3}, {%4,%5,%6,%7}, {%8,%9}, {%0,%1,%2,%3};"
        : "+f"(c[0]), "+f"(c[1]), "+f"(c[2]), "+f"(c[3])
        : "r"(a[0]), "r"(a[1]), "r"(a[2]), "r"(a[3]), "r"(b0), "r"(b1));
}

// ---------------- weight transpose + fp16 convert ----------------
// WqT[d,j] = Wq[j,d]; WkT[e,j] = Wk[j,e]
__global__ void wtrans(const float* __restrict__ Wq, const float* __restrict__ Wk,
                       __half* __restrict__ WqT, __half* __restrict__ WkT) {
    __shared__ float tile[32][33];
    const float* src = blockIdx.z ? Wk : Wq;
    __half* dst = blockIdx.z ? WkT : WqT;
    const int j0 = blockIdx.y * 32, d0 = blockIdx.x * 32;
#pragma unroll
    for (int i = 0; i < 4; ++i) {
        int j = threadIdx.y + i * 8;
        tile[j][threadIdx.x] = src[(j0 + j) * KD + d0 + threadIdx.x];
    }
    __syncthreads();
#pragma unroll
    for (int i = 0; i < 4; ++i) {
        int d = threadIdx.y + i * 8;
        dst[(size_t)(d0 + d) * KD + j0 + threadIdx.x] =
            __float2half(tile[threadIdx.x][d]);
    }
}

// ---------------- bias-derived vectors: w_u = bk@Wq, w_v = bq@Wk, c = bq.bk --
__global__ void uvc_kernel(const float* __restrict__ Wq, const float* __restrict__ Wk,
                           const float* __restrict__ bq, const float* __restrict__ bk,
                           float* __restrict__ wu, float* __restrict__ wv) {
    const int b = blockIdx.x;
    if (b < 2) {
        int d = b * 256 + threadIdx.x;
        float s = 0.f;
        for (int j = 0; j < KD; ++j) s += bk[j] * Wq[j * KD + d];
        wu[d] = s;
    } else if (b < 4) {
        int d = (b - 2) * 256 + threadIdx.x;
        float s = 0.f;
        for (int j = 0; j < KD; ++j) s += bq[j] * Wk[j * KD + d];
        wv[d] = s;
    } else {
        __shared__ float red[256];
        float s = bq[threadIdx.x] * bk[threadIdx.x] +
                  bq[threadIdx.x + 256] * bk[threadIdx.x + 256];
        red[threadIdx.x] = s;
        __syncthreads();
        for (int o = 128; o; o >>= 1) {
            if (threadIdx.x < (unsigned)o) red[threadIdx.x] += red[threadIdx.x + o];
            __syncthreads();
        }
        if (threadIdx.x == 0) g_c = red[0];
    }
}

// ---------------- fused fp32->fp16 convert + row GEMV (u, v) ----------------
// one warp per row; rows [0,MQ_) = xq -> u, rows [MQ_, MQ_+MK_) = xk -> v
__global__ void conv_gemv(const float4* __restrict__ xq, const float4* __restrict__ xk) {
    const int gw = (blockIdx.x * blockDim.x + threadIdx.x) >> 5;
    const int l = threadIdx.x & 31;
    const bool isQ = gw < MQ_;
    const int r = isQ ? gw : gw - MQ_;
    const float4* src = isQ ? xq : xk;
    const float4* w4 = (const float4*)(isQ ? g_wu : g_wv);
    __half2* dst = (__half2*)(isQ ? g_xq16 : g_xk16);
    float dot = 0.f;
#pragma unroll
    for (int i = 0; i < 4; ++i) {
        const int idx = r * (KD / 4) + l + i * 32;
        float4 a = src[idx];
        float4 w = w4[l + i * 32];
        dst[idx * 2 + 0] = __floats2half2_rn(a.x, a.y);
        dst[idx * 2 + 1] = __floats2half2_rn(a.z, a.w);
        dot += a.x * w.x + a.y * w.y + a.z * w.z + a.w * w.w;
    }
#pragma unroll
    for (int o = 16; o; o >>= 1) dot += __shfl_xor_sync(0xffffffff, dot, o);
    if (l == 0) {
        if (isQ) g_u[r] = (dot + g_c) * 0.015625f;
        else     g_v[r] = dot * 0.015625f;
    }
}

// ---------------- fp16 GEMM:  D[m,n] = sum_k A[m,k] * B[n,k]  ----------------
// MODE 0: outH = D * scale (fp16)
// MODE 1: outF = D + u[row] + v[col], mask -> -inf (fp32)
template <int MODE>
__global__ __launch_bounds__(256, 2) void hgemm(
    const __half* __restrict__ A, const __half* __restrict__ Bm,
    __half* __restrict__ outH, float* __restrict__ outF,
    const unsigned char* __restrict__ mask,
    float scale, int aRows, int bRows, int outLd) {
    extern __shared__ char smem[];
    const uint32_t sb = smem_u32(smem);
    const int tid = threadIdx.x;
    const int wid = tid >> 5;
    const int l = tid & 31;
    const int wm = wid >> 2;      // 0..1 : 64-row slab
    const int wn = wid & 3;       // 0..3 : 32-col slab
    const int mt = blockIdx.x, nt = blockIdx.y, bz = blockIdx.z;

    const size_t aBase = ((size_t)bz * aRows + (size_t)mt * BM) * KD;
    const size_t bBase = ((size_t)bz * bRows + (size_t)nt * BN) * KD;

    float acc[4][4][4];
#pragma unroll
    for (int i = 0; i < 4; ++i)
#pragma unroll
        for (int j = 0; j < 4; ++j)
#pragma unroll
            for (int c = 0; c < 4; ++c) acc[i][j][c] = 0.f;

    const int aRow = wm * 64 + (l & 15);
    const int aKsel = ((l >> 4) & 1) * 16;
    const int bRow = wn * 32 + (l & 7) + ((l >> 4) & 1) * 8;
    const int bKsel = ((l >> 3) & 1) * 16;

    auto load_tile = [&](int stg, int k0) {
        const uint32_t sA = sb + stg * STAGE_BYTES;
        const uint32_t sB = sA + BM * 128;
#pragma unroll
        for (int t = 0; t < 4; ++t) {
            int i = tid + t * 256;
            int r = i >> 3, c = i & 7;
            cp16(sA + SWZ((uint32_t)(r * 128 + c * 16)),
                 A + aBase + (size_t)r * KD + k0 + c * 8);
        }
#pragma unroll
        for (int t = 0; t < 4; ++t) {
            int i = tid + t * 256;
            int r = i >> 3, c = i & 7;
            cp16(sB + SWZ((uint32_t)(r * 128 + c * 16)),
                 Bm + bBase + (size_t)r * KD + k0 + c * 8);
        }
    };

    load_tile(0, 0);
    CP_COMMIT();

    int stg = 0;
    for (int ch = 0; ch < NCH; ++ch) {
        if (ch + 1 < NCH) {
            load_tile(stg ^ 1, (ch + 1) * BK);
            CP_COMMIT();
            CP_WAIT1();
        } else {
            CP_WAIT0();
        }
        __syncthreads();

        const uint32_t sA = sb + stg * STAGE_BYTES;
        const uint32_t sB = sA + BM * 128;
#pragma unroll
        for (int ks = 0; ks < BK / 16; ++ks) {
            uint32_t afr[4][4];
            uint32_t bfr[2][4];
#pragma unroll
            for (int mi = 0; mi < 4; ++mi)
                ldsm4(afr[mi], sA + SWZ((uint32_t)((aRow + mi * 16) * 128 +
                                                   ks * 32 + aKsel)));
#pragma unroll
            for (int nb = 0; nb < 2; ++nb)
                ldsm4(bfr[nb], sB + SWZ((uint32_t)((bRow + nb * 16) * 128 +
                                                   ks * 32 + bKsel)));
#pragma unroll
            for (int mi = 0; mi < 4; ++mi)
#pragma unroll
                for (int ni = 0; ni < 4; ++ni)
                    mma16816(acc[mi][ni], afr[mi], bfr[ni >> 1][(ni & 1) * 2],
                             bfr[ni >> 1][(ni & 1) * 2 + 1]);
        }
        __syncthreads();
        stg ^= 1;
    }

    // ---------------- epilogue ----------------
    const int gid = l >> 2, tig = l & 3;
#pragma unroll
    for (int mi = 0; mi < 4; ++mi) {
#pragma unroll
        for (int ni = 0; ni < 4; ++ni) {
            const int col = nt * BN + wn * 32 + ni * 8 + tig * 2;
#pragma unroll
            for (int h = 0; h < 2; ++h) {
                const int row = mt * BM + wm * 64 + mi * 16 + gid + h * 8;
                const size_t rowg = (size_t)bz * aRows + row;
                const float v0 = acc[mi][ni][h * 2 + 0];
                const float v1 = acc[mi][ni][h * 2 + 1];
                if (MODE == 0) {
                    *(__half2*)(outH + rowg * outLd + col) =
                        __floats2half2_rn(v0 * scale, v1 * scale);
                } else {
                    const size_t colg = (size_t)bz * S_ + col;
                    const float uu = g_u[rowg];
                    const float NEG_INF = __int_as_float(0xff800000);
                    float2 o;
                    o.x = mask[colg + 0] ? NEG_INF : v0 + uu + g_v[colg + 0];
                    o.y = mask[colg + 1] ? NEG_INF : v1 + uu + g_v[colg + 1];
                    *(float2*)(outF + rowg * (size_t)S_ + col) = o;
                }
            }
        }
    }
}

// ---------------- host launch ----------------
extern "C" void kernel_launch(void* const* d_in, const int* in_sizes, int n_in,
                              void* d_out, int out_size) {
    const float* query = (const float*)d_in[0];
    const float* keys = (const float*)d_in[1];
    const unsigned char* mask = (const unsigned char*)d_in[2];
    const float* q_w = (const float*)d_in[3];
    const float* q_b = (const float*)d_in[4];
    const float* k_w = (const float*)d_in[5];
    const float* k_b = (const float*)d_in[6];

    void *xq16, *xk16, *wqT, *wkT, *M, *Y, *wu, *wv;
    cudaGetSymbolAddress(&xq16, g_xq16);
    cudaGetSymbolAddress(&xk16, g_xk16);
    cudaGetSymbolAddress(&wqT, g_wqT);
    cudaGetSymbolAddress(&wkT, g_wkT);
    cudaGetSymbolAddress(&M, g_M);
    cudaGetSymbolAddress(&Y, g_Y);
    cudaGetSymbolAddress(&wu, g_wu);
    cudaGetSymbolAddress(&wv, g_wv);

    cudaFuncSetAttribute(hgemm<0>, cudaFuncAttributeMaxDynamicSharedMemorySize,
                         SMEM_BYTES);
    cudaFuncSetAttribute(hgemm<1>, cudaFuncAttributeMaxDynamicSharedMemorySize,
                         SMEM_BYTES);

    // 1) weight transpose + fp16 convert
    wtrans<<<dim3(16, 16, 2), dim3(32, 8)>>>(q_w, k_w, (__half*)wqT, (__half*)wkT);

    // 2) w_u = bk@Wq, w_v = bq@Wk, c = bq.bk
    uvc_kernel<<<5, 256>>>(q_w, k_w, q_b, k_b, (float*)wu, (float*)wv);

    // 3) convert xq/xk to fp16 + per-row GEMVs u, v
    conv_gemv<<<(MQ_ + MK_) / 8, 256>>>((const float4*)query, (const float4*)keys);

    // 4) M'[e,d] = sum_j Wk[j,e] Wq[j,d]    (512x512, fp16)
    hgemm<0><<<dim3(KD / BM, KD / BN, 1), 256, SMEM_BYTES>>>(
        (const __half*)wkT, (const __half*)wqT, (__half*)M, nullptr, nullptr,
        1.0f, KD, KD, KD);

    // 5) Y[t,e] = (xq @ M)/64               (8192x512, fp16)
    hgemm<0><<<dim3(MQ_ / BM, KD / BN, 1), 256, SMEM_BYTES>>>(
        (const __half*)xq16, (const __half*)M, (__half*)Y, nullptr, nullptr,
        0.015625f, MQ_, KD, KD);

    // 6) logits = Y @ xk^T + u[t] + v[s], masked   [4,2048,4096] fp32
    hgemm<1><<<dim3(T_ / BM, S_ / BN, B_), 256, SMEM_BYTES>>>(
        (const __half*)Y, (const __half*)xk16, nullptr, (float*)d_out, mask,
        1.0f, T_, S_, S_);
}

// round 5
// speedup vs baseline: 1.0795x; 1.0726x over previous
#include <cuda_runtime.h>
#include <cuda_fp16.h>
#include <cstdint>

// ---------------- fixed problem sizes ----------------
#define B_   4
#define T_   2048
#define S_   4096
#define KD   512
#define MQ_  (B_*T_)    // 8192
#define MK_  (B_*S_)    // 16384

// ---------------- GEMM tiling ----------------
#define BM 128
#define BN 128
#define BK 64
#define STAGE_BYTES (BM*128 + BN*128)       // 32 KB
#define SMEM_MAIN   (2*STAGE_BYTES)         // 64 KB
#define SMEM_EXTRA  640                     // v tile (512B) + mask tile (128B)
#define SMEM_ALL    (SMEM_MAIN + SMEM_EXTRA)

// ---------------- scratch (device globals; no allocation allowed) ----------------
__device__ __half g_xq16[MQ_ * KD];
__device__ __half g_xk16[MK_ * KD];
__device__ __half g_wqT[KD * KD];
__device__ __half g_wkT[KD * KD];
__device__ float  g_Mf8[8 * KD * KD];   // split-K partials of M'
__device__ __half g_M  [KD * KD];       // M'[e,d] = sum_j Wk[j,e] Wq[j,d]
__device__ __half g_Y  [MQ_ * KD];      // Y[t,e] = xq[t,:] @ M2[:,e] / 64
__device__ float  g_u  [MQ_];
__device__ float  g_v  [MK_];
__device__ float  g_wu [KD];
__device__ float  g_wv [KD];
__device__ float  g_c;

// ---------------- helpers ----------------
#define SWZ(o) ((o) ^ (((o) >> 3) & 0x70))

__device__ __forceinline__ uint32_t smem_u32(const void* p) {
    uint32_t a;
    asm("{ .reg .u64 t; cvta.to.shared.u64 t, %1; cvt.u32.u64 %0, t; }"
        : "=r"(a) : "l"(p));
    return a;
}

__device__ __forceinline__ void cp16(uint32_t s, const void* g) {
    asm volatile("cp.async.cg.shared.global [%0], [%1], 16;" :: "r"(s), "l"(g));
}
#define CP_COMMIT() asm volatile("cp.async.commit_group;" ::: "memory")
#define CP_WAIT0()  asm volatile("cp.async.wait_group 0;" ::: "memory")
#define CP_WAIT1()  asm volatile("cp.async.wait_group 1;" ::: "memory")

__device__ __forceinline__ void ldsm4(uint32_t* r, uint32_t addr) {
    asm volatile("ldmatrix.sync.aligned.m8n8.x4.shared.b16 {%0,%1,%2,%3}, [%4];"
                 : "=r"(r[0]), "=r"(r[1]), "=r"(r[2]), "=r"(r[3]) : "r"(addr));
}

__device__ __forceinline__ void mma16816(float* c, const uint32_t* a,
                                         uint32_t b0, uint32_t b1) {
    asm volatile(
        "mma.sync.aligned.m16n8k16.row.col.f32.f16.f16.f32 "
        "{%0,%1,%2,%3}, {%4,%5,%6,%7}, {%8,%9}, {%0,%1,%2,%3};"
        : "+f"(c[0]), "+f"(c[1]), "+f"(c[2]), "+f"(c[3])
        : "r"(a[0]), "r"(a[1]), "r"(a[2]), "r"(a[3]), "r"(b0), "r"(b1));
}

// ---------------- prep: weight transpose+cvt, wu, wv, c (one launch) --------
// blocks [0,512): transpose tiles. [512,514): wu. [514,516): wv. 516: c.
__global__ void prep_small(const float* __restrict__ Wq, const float* __restrict__ Wk,
                           const float* __restrict__ bq, const float* __restrict__ bk) {
    const int b = blockIdx.x;
    if (b < 512) {
        __shared__ float tile[32][33];
        const int w = b >> 8;                 // 0 = Wq, 1 = Wk
        const int t = b & 255;
        const float* src = w ? Wk : Wq;
        __half* dst = w ? g_wkT : g_wqT;
        const int d0 = (t & 15) * 32, j0 = (t >> 4) * 32;
        const int tx = threadIdx.x & 31, ty = threadIdx.x >> 5;   // 32 x 8
#pragma unroll
        for (int i = 0; i < 4; ++i) {
            int j = ty + i * 8;
            tile[j][tx] = src[(size_t)(j0 + j) * KD + d0 + tx];
        }
        __syncthreads();
#pragma unroll
        for (int i = 0; i < 4; ++i) {
            int d = ty + i * 8;
            dst[(size_t)(d0 + d) * KD + j0 + tx] = __float2half(tile[tx][d]);
        }
    } else if (b < 516) {
        const int which = b - 512;            // 0,1: wu  2,3: wv
        const int d = (which & 1) * 256 + threadIdx.x;
        const float* W = (which < 2) ? Wq : Wk;
        const float* bb = (which < 2) ? bk : bq;
        float* dst = (which < 2) ? g_wu : g_wv;
        float s = 0.f;
        for (int j = 0; j < KD; ++j) s += bb[j] * W[(size_t)j * KD + d];
        dst[d] = s;
    } else {
        __shared__ float red[256];
        float s = bq[threadIdx.x] * bk[threadIdx.x] +
                  bq[threadIdx.x + 256] * bk[threadIdx.x + 256];
        red[threadIdx.x] = s;
        __syncthreads();
        for (int o = 128; o; o >>= 1) {
            if (threadIdx.x < (unsigned)o) red[threadIdx.x] += red[threadIdx.x + o];
            __syncthreads();
        }
        if (threadIdx.x == 0) g_c = red[0];
    }
}

// ---------------- fused fp32->fp16 convert + row GEMV (u, v) ----------------
__global__ void conv_gemv(const float4* __restrict__ xq, const float4* __restrict__ xk) {
    const int gw = (blockIdx.x * blockDim.x + threadIdx.x) >> 5;
    const int l = threadIdx.x & 31;
    const bool isQ = gw < MQ_;
    const int r = isQ ? gw : gw - MQ_;
    const float4* src = isQ ? xq : xk;
    const float4* w4 = (const float4*)(isQ ? g_wu : g_wv);
    __half2* dst = (__half2*)(isQ ? g_xq16 : g_xk16);
    float dot = 0.f;
#pragma unroll
    for (int i = 0; i < 4; ++i) {
        const int idx = r * (KD / 4) + l + i * 32;
        float4 a = src[idx];
        float4 w = w4[l + i * 32];
        dst[idx * 2 + 0] = __floats2half2_rn(a.x, a.y);
        dst[idx * 2 + 1] = __floats2half2_rn(a.z, a.w);
        dot += a.x * w.x + a.y * w.y + a.z * w.z + a.w * w.w;
    }
#pragma unroll
    for (int o = 16; o; o >>= 1) dot += __shfl_xor_sync(0xffffffff, dot, o);
    if (l == 0) {
        if (isQ) g_u[r] = (dot + g_c) * 0.015625f;
        else     g_v[r] = dot * 0.015625f;
    }
}

// ---------------- sum split-K partials of M, convert to fp16 ----------------
__global__ void m_cvt() {
    const int i = blockIdx.x * blockDim.x + threadIdx.x;   // 262144 threads
    float s = 0.f;
#pragma unroll
    for (int z = 0; z < 8; ++z) s += g_Mf8[z * (KD * KD) + i];
    g_M[i] = __float2half(s);
}

// ---------------- fp16 GEMM:  D[m,n] = sum_k A[m,k] * B[n,k]  ----------------
// MODE 0: outH = D * scale (fp16)
// MODE 1: outF = D + u[row] + v[col], mask -> -inf (fp32); v/mask smem-cached
// MODE 2: split-K slice (nch=1, kStart=bz*BK), fp32 store to outMf slice bz
template <int MODE>
__global__ __launch_bounds__(256, 2) void hgemm(
    const __half* __restrict__ A, const __half* __restrict__ Bm,
    __half* __restrict__ outH, float* __restrict__ outF,
    float* __restrict__ outMf, const unsigned char* __restrict__ mask,
    float scale, int aRows, int bRows, int outLd, int nch) {
    extern __shared__ char smem[];
    const uint32_t sb = smem_u32(smem);
    const int tid = threadIdx.x;
    const int wid = tid >> 5;
    const int l = tid & 31;
    const int wm = wid >> 2;
    const int wn = wid & 3;
    const int mt = blockIdx.x, nt = blockIdx.y, bz = blockIdx.z;

    size_t aBase, bBase;
    int kStart;
    if (MODE == 2) {
        aBase = (size_t)mt * BM * KD;
        bBase = (size_t)nt * BN * KD;
        kStart = bz * BK;
    } else {
        aBase = ((size_t)bz * aRows + (size_t)mt * BM) * KD;
        bBase = ((size_t)bz * bRows + (size_t)nt * BN) * KD;
        kStart = 0;
    }

    // MODE 1: cache v tile + mask tile in smem (region after the two stages)
    float* sv = (float*)(smem + SMEM_MAIN);
    unsigned char* sm = (unsigned char*)(smem + SMEM_MAIN + 512);
    if (MODE == 1 && tid < 128) {
        const size_t colg = (size_t)bz * S_ + (size_t)nt * BN + tid;
        sv[tid] = g_v[colg];
        sm[tid] = mask[colg];
    }

    float acc[4][4][4];
#pragma unroll
    for (int i = 0; i < 4; ++i)
#pragma unroll
        for (int j = 0; j < 4; ++j)
#pragma unroll
            for (int c = 0; c < 4; ++c) acc[i][j][c] = 0.f;

    const int aRow = wm * 64 + (l & 15);
    const int aKsel = ((l >> 4) & 1) * 16;
    const int bRow = wn * 32 + (l & 7) + ((l >> 4) & 1) * 8;
    const int bKsel = ((l >> 3) & 1) * 16;

    auto load_tile = [&](int stg, int k0) {
        const uint32_t sA = sb + stg * STAGE_BYTES;
        const uint32_t sB = sA + BM * 128;
#pragma unroll
        for (int t = 0; t < 4; ++t) {
            int i = tid + t * 256;
            int r = i >> 3, c = i & 7;
            cp16(sA + SWZ((uint32_t)(r * 128 + c * 16)),
                 A + aBase + (size_t)r * KD + k0 + c * 8);
        }
#pragma unroll
        for (int t = 0; t < 4; ++t) {
            int i = tid + t * 256;
            int r = i >> 3, c = i & 7;
            cp16(sB + SWZ((uint32_t)(r * 128 + c * 16)),
                 Bm + bBase + (size_t)r * KD + k0 + c * 8);
        }
    };

    load_tile(0, kStart);
    CP_COMMIT();

    int stg = 0;
    for (int ch = 0; ch < nch; ++ch) {
        if (ch + 1 < nch) {
            load_tile(stg ^ 1, kStart + (ch + 1) * BK);
            CP_COMMIT();
            CP_WAIT1();
        } else {
            CP_WAIT0();
        }
        __syncthreads();

        const uint32_t sA = sb + stg * STAGE_BYTES;
        const uint32_t sB = sA + BM * 128;
#pragma unroll
        for (int ks = 0; ks < BK / 16; ++ks) {
            uint32_t afr[4][4];
            uint32_t bfr[2][4];
#pragma unroll
            for (int mi = 0; mi < 4; ++mi)
                ldsm4(afr[mi], sA + SWZ((uint32_t)((aRow + mi * 16) * 128 +
                                                   ks * 32 + aKsel)));
#pragma unroll
            for (int nb = 0; nb < 2; ++nb)
                ldsm4(bfr[nb], sB + SWZ((uint32_t)((bRow + nb * 16) * 128 +
                                                   ks * 32 + bKsel)));
#pragma unroll
            for (int mi = 0; mi < 4; ++mi)
#pragma unroll
                for (int ni = 0; ni < 4; ++ni)
                    mma16816(acc[mi][ni], afr[mi], bfr[ni >> 1][(ni & 1) * 2],
                             bfr[ni >> 1][(ni & 1) * 2 + 1]);
        }
        __syncthreads();
        stg ^= 1;
    }

    // ---------------- epilogue ----------------
    const int gid = l >> 2, tig = l & 3;
#pragma unroll
    for (int mi = 0; mi < 4; ++mi) {
#pragma unroll
        for (int h = 0; h < 2; ++h) {
            const int row = mt * BM + wm * 64 + mi * 16 + gid + h * 8;
            const size_t rowg =
                (MODE == 2) ? (size_t)row : (size_t)bz * aRows + row;
            float uu = 0.f;
            if (MODE == 1) uu = g_u[rowg];
#pragma unroll
            for (int ni = 0; ni < 4; ++ni) {
                const int lcol = wn * 32 + ni * 8 + tig * 2;
                const int col = nt * BN + lcol;
                const float v0 = acc[mi][ni][h * 2 + 0];
                const float v1 = acc[mi][ni][h * 2 + 1];
                if (MODE == 0) {
                    *(__half2*)(outH + rowg * outLd + col) =
                        __floats2half2_rn(v0 * scale, v1 * scale);
                } else if (MODE == 2) {
                    float* dst = outMf + (size_t)bz * (KD * KD) +
                                 rowg * outLd + col;
                    dst[0] = v0;
                    dst[1] = v1;
                } else {
                    const float NEG_INF = __int_as_float(0xff800000);
                    float2 o;
                    o.x = sm[lcol + 0] ? NEG_INF : v0 + uu + sv[lcol + 0];
                    o.y = sm[lcol + 1] ? NEG_INF : v1 + uu + sv[lcol + 1];
                    *(float2*)(outF + rowg * (size_t)S_ + col) = o;
                }
            }
        }
    }
}

// ---------------- host launch ----------------
extern "C" void kernel_launch(void* const* d_in, const int* in_sizes, int n_in,
                              void* d_out, int out_size) {
    const float* query = (const float*)d_in[0];
    const float* keys = (const float*)d_in[1];
    const unsigned char* mask = (const unsigned char*)d_in[2];
    const float* q_w = (const float*)d_in[3];
    const float* q_b = (const float*)d_in[4];
    const float* k_w = (const float*)d_in[5];
    const float* k_b = (const float*)d_in[6];

    void *xq16, *xk16, *wqT, *wkT, *Mf8, *M, *Y;
    cudaGetSymbolAddress(&xq16, g_xq16);
    cudaGetSymbolAddress(&xk16, g_xk16);
    cudaGetSymbolAddress(&wqT, g_wqT);
    cudaGetSymbolAddress(&wkT, g_wkT);
    cudaGetSymbolAddress(&Mf8, g_Mf8);
    cudaGetSymbolAddress(&M, g_M);
    cudaGetSymbolAddress(&Y, g_Y);

    cudaFuncSetAttribute(hgemm<0>, cudaFuncAttributeMaxDynamicSharedMemorySize,
                         SMEM_ALL);
    cudaFuncSetAttribute(hgemm<1>, cudaFuncAttributeMaxDynamicSharedMemorySize,
                         SMEM_ALL);
    cudaFuncSetAttribute(hgemm<2>, cudaFuncAttributeMaxDynamicSharedMemorySize,
                         SMEM_ALL);

    // 1) weight transpose/convert + wu, wv, c (single launch)
    prep_small<<<517, 256>>>(q_w, k_w, q_b, k_b);

    // 2) convert xq/xk to fp16 + per-row GEMVs u, v
    conv_gemv<<<(MQ_ + MK_) / 8, 256>>>((const float4*)query, (const float4*)keys);

    // 3) M partials: M'[e,d] = sum_j Wk[j,e] Wq[j,d], split-K over 8 slices
    hgemm<2><<<dim3(KD / BM, KD / BN, 8), 256, SMEM_ALL>>>(
        (const __half*)wkT, (const __half*)wqT, nullptr, nullptr, (float*)Mf8,
        nullptr, 1.0f, KD, KD, KD, 1);

    // 4) reduce partials -> fp16 M
    m_cvt<<<(KD * KD) / 256, 256>>>();

    // 5) Y = (xq @ M2)/64    [8192 x 512] fp16
    hgemm<0><<<dim3(MQ_ / BM, KD / BN, 1), 256, SMEM_ALL>>>(
        (const __half*)xq16, (const __half*)M, (__half*)Y, nullptr, nullptr,
        nullptr, 0.015625f, MQ_, KD, KD, KD / BK);

    // 6) logits = Y @ xk^T + u[t] + v[s], masked   [4,2048,4096] fp32
    hgemm<1><<<dim3(T_ / BM, S_ / BN, B_), 256, SMEM_ALL>>>(
        (const __half*)Y, (const __half*)xk16, nullptr, (float*)d_out, nullptr,
        mask, 1.0f, T_, S_, S_, KD / BK);
}